// round 1
// baseline (speedup 1.0000x reference)
#include <cuda_runtime.h>
#include <math.h>

#define BATCH 4096
#define FDIM  512
#define NJ    16
#define NM    64
#define NU    512
#define JM    (NJ*NM)   // 1024

// ---- scratch (device globals; no allocation allowed) ----
__device__ float g_Khd[(size_t)BATCH * JM];  // 16 MB
__device__ float g_h2[BATCH];
__device__ float g_d2[JM];
__device__ float g_kdd[NJ];
__device__ float g_prob[BATCH * NJ];

// gauss: exp(-sq / (2*sigma^2)), sigma=0.5 -> exp(-2*sq)

// ============================================================
// Kernel 1: row sum-of-squares for h (rows 0..B-1) and domains (rows B..B+JM-1)
// ============================================================
__global__ void sumsq_kernel(const float* __restrict__ h, const float* __restrict__ dom) {
    int r = blockIdx.x;
    const float* p;
    float* o;
    if (r < BATCH) { p = h + (size_t)r * FDIM;           o = &g_h2[r]; }
    else           { p = dom + (size_t)(r - BATCH) * FDIM; o = &g_d2[r - BATCH]; }
    int t = threadIdx.x;                       // 128 threads * 4 floats = 512
    float4 v = *(const float4*)&p[t << 2];
    float s = v.x*v.x + v.y*v.y + v.z*v.z + v.w*v.w;
    #pragma unroll
    for (int off = 16; off; off >>= 1) s += __shfl_xor_sync(0xffffffffu, s, off);
    __shared__ float ws[4];
    if ((t & 31) == 0) ws[t >> 5] = s;
    __syncthreads();
    if (t == 0) *o = ws[0] + ws[1] + ws[2] + ws[3];
}

// ============================================================
// Kernel 2: k_dd_mean[j] = mean_{m,n} exp(-2*(d2m + d2n - 2*<dm,dn>))
// one block per j, 4 warps, warp handles rows m = warp, warp+4, ...
// ============================================================
__global__ void kdd_kernel(const float* __restrict__ dom) {
    int j = blockIdx.x;
    int warp = threadIdx.x >> 5, lane = threadIdx.x & 31;
    const float* dj = dom + (size_t)j * NM * FDIM;
    float acc = 0.f;
    for (int m = warp; m < NM; m += 4) {
        float4 dm[4];
        #pragma unroll
        for (int q = 0; q < 4; q++)
            dm[q] = *(const float4*)&dj[(size_t)m * FDIM + q * 128 + (lane << 2)];
        float d2m = g_d2[j * NM + m];
        for (int n = 0; n < NM; n++) {
            float dot = 0.f;
            #pragma unroll
            for (int q = 0; q < 4; q++) {
                float4 dn = *(const float4*)&dj[(size_t)n * FDIM + q * 128 + (lane << 2)];
                dot += dm[q].x*dn.x + dm[q].y*dn.y + dm[q].z*dn.z + dm[q].w*dn.w;
            }
            #pragma unroll
            for (int off = 16; off; off >>= 1) dot += __shfl_xor_sync(0xffffffffu, dot, off);
            float dd = d2m + g_d2[j * NM + n] - 2.f * dot;
            acc += expf(-2.f * dd);   // identical across lanes after reduce
        }
    }
    __shared__ float ws[4];
    if (lane == 0) ws[warp] = acc;
    __syncthreads();
    if (threadIdx.x == 0) g_kdd[j] = (ws[0] + ws[1] + ws[2] + ws[3]) / (float)(NM * NM);
}

// ---- swizzled transposed tile addressing: tile is [32 k][64 m] floats ----
// element (k,m) at: k*64 + (((m>>2) ^ (k&15)) << 2) + (m&3)
// float4 read at (k, 4*g): offset k*64 + ((g ^ (k&15))<<2)  -> 16B aligned, 2-phase
__device__ __forceinline__ int swz(int k, int m) {
    return (k << 6) + ((((m >> 2) ^ (k & 15)) << 2) | (m & 3));
}

// ============================================================
// Kernel 3: GEMM1  K_hd[b, jm] = exp(-2*(h2[b] + d2[jm] - 2 * h[b,:].dot(dom[jm,:])))
// 64x64 tile, BK=32, 256 threads, 4x4 per thread
// ============================================================
__global__ void __launch_bounds__(256) gemm_khd(const float* __restrict__ h,
                                                const float* __restrict__ dom) {
    __shared__ float As[32 * 64];
    __shared__ float Bs[32 * 64];
    int tid = threadIdx.x;
    int tx = tid & 15, ty = tid >> 4;
    int n0 = blockIdx.x << 6;
    int m0 = blockIdx.y << 6;
    float acc[4][4] = {};

    for (int k0 = 0; k0 < FDIM; k0 += 32) {
        #pragma unroll
        for (int i = 0; i < 2; i++) {
            int lin = tid + (i << 8);          // 0..511
            int r = lin >> 3;                  // 0..63 (tile row)
            int c4 = (lin & 7) << 2;           // 0..28 (tile k, steps of 4)
            float4 va = *(const float4*)&h[(size_t)(m0 + r) * FDIM + k0 + c4];
            As[swz(c4 + 0, r)] = va.x; As[swz(c4 + 1, r)] = va.y;
            As[swz(c4 + 2, r)] = va.z; As[swz(c4 + 3, r)] = va.w;
            float4 vb = *(const float4*)&dom[(size_t)(n0 + r) * FDIM + k0 + c4];
            Bs[swz(c4 + 0, r)] = vb.x; Bs[swz(c4 + 1, r)] = vb.y;
            Bs[swz(c4 + 2, r)] = vb.z; Bs[swz(c4 + 3, r)] = vb.w;
        }
        __syncthreads();
        #pragma unroll
        for (int k = 0; k < 32; k++) {
            float4 a = *(const float4*)&As[swz(k, ty << 2)];
            float4 b = *(const float4*)&Bs[swz(k, tx << 2)];
            acc[0][0] += a.x*b.x; acc[0][1] += a.x*b.y; acc[0][2] += a.x*b.z; acc[0][3] += a.x*b.w;
            acc[1][0] += a.y*b.x; acc[1][1] += a.y*b.y; acc[1][2] += a.y*b.z; acc[1][3] += a.y*b.w;
            acc[2][0] += a.z*b.x; acc[2][1] += a.z*b.y; acc[2][2] += a.z*b.z; acc[2][3] += a.z*b.w;
            acc[3][0] += a.w*b.x; acc[3][1] += a.w*b.y; acc[3][2] += a.w*b.z; acc[3][3] += a.w*b.w;
        }
        __syncthreads();
    }

    int c = n0 + (tx << 2);
    float4 d2v = *(const float4*)&g_d2[c];
    #pragma unroll
    for (int i = 0; i < 4; i++) {
        int r = m0 + (ty << 2) + i;
        float h2r = g_h2[r];
        float4 o;
        o.x = expf(-2.f * (h2r + d2v.x - 2.f * acc[i][0]));
        o.y = expf(-2.f * (h2r + d2v.y - 2.f * acc[i][1]));
        o.z = expf(-2.f * (h2r + d2v.z - 2.f * acc[i][2]));
        o.w = expf(-2.f * (h2r + d2v.w - 2.f * acc[i][3]));
        *(float4*)&g_Khd[(size_t)r * JM + c] = o;
    }
}

// ============================================================
// Kernel 4: per-row softmax -> prob[b, j]
// one warp per row
// ============================================================
__global__ void prob_kernel() {
    int row = (blockIdx.x * blockDim.x + threadIdx.x) >> 5;
    int lane = threadIdx.x & 31;
    if (row >= BATCH) return;
    const float* r = g_Khd + (size_t)row * JM;
    float jsum[NJ] = {};
    #pragma unroll
    for (int i = 0; i < 32; i++) {
        float v = r[(i << 5) + lane];   // j = (i*32+lane)/64 == i>>1
        jsum[i >> 1] += v;
    }
    float e[NJ];
    float mx = -1e30f;
    #pragma unroll
    for (int j = 0; j < NJ; j++) {
        float s = jsum[j];
        #pragma unroll
        for (int off = 16; off; off >>= 1) s += __shfl_xor_sync(0xffffffffu, s, off);
        float mmd = 1.0f - 2.0f * (s * (1.0f / 64.0f)) + g_kdd[j];
        e[j] = -mmd;                      // logit (SOFTNESS = 1)
        mx = fmaxf(mx, e[j]);
    }
    float den = 0.f;
    #pragma unroll
    for (int j = 0; j < NJ; j++) { e[j] = expf(e[j] - mx); den += e[j]; }
    float inv = 1.0f / den;
    if (lane == 0) {
        #pragma unroll
        for (int j = 0; j < NJ; j++) g_prob[row * NJ + j] = e[j] * inv;
    }
}

// ============================================================
// Kernel 5: GEMM2  out[b,u] = sum_{jm} (prob[b,jm/64]*Khd[b,jm]) * W[jm,u]
//                           + sum_j prob[b,j]*bvec[j,u]
// ============================================================
__global__ void __launch_bounds__(256) gemm_out(const float* __restrict__ W,
                                                const float* __restrict__ bvec,
                                                float* __restrict__ out) {
    __shared__ float As[32 * 64];        // swizzled transposed, prob-scaled Khd
    __shared__ float Bs[32][64];         // W tile, direct layout
    __shared__ float s_prob[64][NJ];
    __shared__ float s_b[NJ][64];
    int tid = threadIdx.x;
    int tx = tid & 15, ty = tid >> 4;
    int n0 = blockIdx.x << 6;
    int m0 = blockIdx.y << 6;

    for (int i = tid; i < 64 * NJ; i += 256)
        s_prob[i >> 4][i & 15] = g_prob[(m0 + (i >> 4)) * NJ + (i & 15)];
    for (int i = tid; i < NJ * 64; i += 256)
        s_b[i >> 6][i & 63] = bvec[(size_t)(i >> 6) * NU + n0 + (i & 63)];
    __syncthreads();

    float acc[4][4] = {};
    for (int k0 = 0; k0 < JM; k0 += 32) {
        int jt = k0 >> 6;   // constant j for this whole k-tile (32 | k0, 64-aligned bands)
        #pragma unroll
        for (int i = 0; i < 2; i++) {
            int lin = tid + (i << 8);
            int r = lin >> 3;
            int c4 = (lin & 7) << 2;
            float4 va = *(const float4*)&g_Khd[(size_t)(m0 + r) * JM + k0 + c4];
            float s = s_prob[r][jt];
            As[swz(c4 + 0, r)] = va.x * s; As[swz(c4 + 1, r)] = va.y * s;
            As[swz(c4 + 2, r)] = va.z * s; As[swz(c4 + 3, r)] = va.w * s;
        }
        #pragma unroll
        for (int i = 0; i < 2; i++) {
            int lin = tid + (i << 8);
            int r = lin >> 4;                  // 0..31 (k)
            int c4 = (lin & 15) << 2;          // 0..60 (u)
            *(float4*)&Bs[r][c4] = *(const float4*)&W[(size_t)(k0 + r) * NU + n0 + c4];
        }
        __syncthreads();
        #pragma unroll
        for (int k = 0; k < 32; k++) {
            float4 a = *(const float4*)&As[swz(k, ty << 2)];
            float4 b = *(const float4*)&Bs[k][tx << 2];
            acc[0][0] += a.x*b.x; acc[0][1] += a.x*b.y; acc[0][2] += a.x*b.z; acc[0][3] += a.x*b.w;
            acc[1][0] += a.y*b.x; acc[1][1] += a.y*b.y; acc[1][2] += a.y*b.z; acc[1][3] += a.y*b.w;
            acc[2][0] += a.z*b.x; acc[2][1] += a.z*b.y; acc[2][2] += a.z*b.z; acc[2][3] += a.z*b.w;
            acc[3][0] += a.w*b.x; acc[3][1] += a.w*b.y; acc[3][2] += a.w*b.z; acc[3][3] += a.w*b.w;
        }
        __syncthreads();
    }

    int c = tx << 2;
    #pragma unroll
    for (int i = 0; i < 4; i++) {
        int rl = (ty << 2) + i;
        float4 o;
        o.x = acc[i][0]; o.y = acc[i][1]; o.z = acc[i][2]; o.w = acc[i][3];
        #pragma unroll
        for (int j = 0; j < NJ; j++) {
            float p = s_prob[rl][j];
            o.x += p * s_b[j][c + 0];
            o.y += p * s_b[j][c + 1];
            o.z += p * s_b[j][c + 2];
            o.w += p * s_b[j][c + 3];
        }
        *(float4*)&out[(size_t)(m0 + rl) * NU + n0 + c] = o;
    }
}

// ============================================================
extern "C" void kernel_launch(void* const* d_in, const int* in_sizes, int n_in,
                              void* d_out, int out_size) {
    const float* h    = (const float*)d_in[0];   // [B, F]
    const float* dom  = (const float*)d_in[1];   // [J, M, F]
    const float* W    = (const float*)d_in[2];   // [J, M, U]
    const float* bvec = (const float*)d_in[3];   // [J, U]
    float* out = (float*)d_out;                  // [B, U]

    sumsq_kernel<<<BATCH + JM, 128>>>(h, dom);
    kdd_kernel<<<NJ, 128>>>(dom);
    gemm_khd<<<dim3(JM / 64, BATCH / 64), 256>>>(h, dom);
    prob_kernel<<<(BATCH * 32) / 256, 256>>>();
    gemm_out<<<dim3(NU / 64, BATCH / 64), 256>>>(W, bvec, out);
}

// round 2
// speedup vs baseline: 4.4534x; 4.4534x over previous
#include <cuda_runtime.h>
#include <cuda_bf16.h>
#include <math.h>
#include <stdint.h>

#define BATCH 4096
#define FDIM  512
#define NJ    16
#define NM    64
#define NU    512
#define JM    (NJ*NM)   // 1024

// ---- scratch (device globals; no allocation allowed) ----
__device__ __nv_bfloat16 g_hb[(size_t)BATCH * FDIM];   // 4 MB
__device__ __nv_bfloat16 g_db[(size_t)JM * FDIM];      // 1 MB
__device__ __nv_bfloat16 g_Wb[(size_t)JM * NU];        // 1 MB
__device__ __nv_bfloat16 g_Khd[(size_t)BATCH * JM];    // 8 MB
__device__ float g_h2[BATCH];
__device__ float g_d2[JM];
__device__ float g_kddp[NJ * 8];
__device__ float g_prob[BATCH * NJ];

// ================= PTX helpers =================
__device__ __forceinline__ void cp16(uint32_t dst, const void* src) {
    asm volatile("cp.async.cg.shared.global [%0], [%1], 16;\n" :: "r"(dst), "l"(src));
}
__device__ __forceinline__ void cp_commit() { asm volatile("cp.async.commit_group;\n"); }
template <int N> __device__ __forceinline__ void cp_wait() {
    asm volatile("cp.async.wait_group %0;\n" :: "n"(N));
}
__device__ __forceinline__ void ldm_x4(uint32_t a[4], uint32_t addr) {
    asm volatile("ldmatrix.sync.aligned.m8n8.x4.shared.b16 {%0,%1,%2,%3}, [%4];\n"
                 : "=r"(a[0]), "=r"(a[1]), "=r"(a[2]), "=r"(a[3]) : "r"(addr));
}
__device__ __forceinline__ void ldm_x4t(uint32_t a[4], uint32_t addr) {
    asm volatile("ldmatrix.sync.aligned.m8n8.x4.trans.shared.b16 {%0,%1,%2,%3}, [%4];\n"
                 : "=r"(a[0]), "=r"(a[1]), "=r"(a[2]), "=r"(a[3]) : "r"(addr));
}
__device__ __forceinline__ void mma_bf16(float c[4], const uint32_t a[4], uint32_t b0, uint32_t b1) {
    asm volatile(
        "mma.sync.aligned.m16n8k16.row.col.f32.bf16.bf16.f32 "
        "{%0,%1,%2,%3}, {%4,%5,%6,%7}, {%8,%9}, {%0,%1,%2,%3};\n"
        : "+f"(c[0]), "+f"(c[1]), "+f"(c[2]), "+f"(c[3])
        : "r"(a[0]), "r"(a[1]), "r"(a[2]), "r"(a[3]), "r"(b0), "r"(b1));
}

// ================= Kernel: fp32 -> bf16 conversion =================
__global__ void convert_kernel(const float* __restrict__ h,
                               const float* __restrict__ dom,
                               const float* __restrict__ W) {
    size_t i = ((size_t)blockIdx.x * blockDim.x + threadIdx.x) * 8;
    const size_t NH = (size_t)BATCH * FDIM;
    const size_t ND = (size_t)JM * FDIM;
    const size_t NW = (size_t)JM * NU;
    const float* src;
    __nv_bfloat16* dst;
    if (i < NH)               { src = h + i;             dst = g_hb + i; }
    else if (i < NH + ND)     { src = dom + (i - NH);    dst = g_db + (i - NH); }
    else if (i < NH + ND + NW){ src = W + (i - NH - ND); dst = g_Wb + (i - NH - ND); }
    else return;
    float4 a = *(const float4*)src;
    float4 b = *(const float4*)(src + 4);
    __nv_bfloat162 o0 = __floats2bfloat162_rn(a.x, a.y);
    __nv_bfloat162 o1 = __floats2bfloat162_rn(a.z, a.w);
    __nv_bfloat162 o2 = __floats2bfloat162_rn(b.x, b.y);
    __nv_bfloat162 o3 = __floats2bfloat162_rn(b.z, b.w);
    uint4 u;
    u.x = *(uint32_t*)&o0; u.y = *(uint32_t*)&o1;
    u.z = *(uint32_t*)&o2; u.w = *(uint32_t*)&o3;
    *(uint4*)dst = u;
}

// ================= Kernel: row sum of squares (fp32) =================
__global__ void sumsq_kernel(const float* __restrict__ h, const float* __restrict__ dom) {
    int r = blockIdx.x;
    const float* p;
    float* o;
    if (r < BATCH) { p = h + (size_t)r * FDIM;             o = &g_h2[r]; }
    else           { p = dom + (size_t)(r - BATCH) * FDIM; o = &g_d2[r - BATCH]; }
    int t = threadIdx.x;
    float4 v = *(const float4*)&p[t << 2];
    float s = v.x*v.x + v.y*v.y + v.z*v.z + v.w*v.w;
    #pragma unroll
    for (int off = 16; off; off >>= 1) s += __shfl_xor_sync(0xffffffffu, s, off);
    __shared__ float ws[4];
    if ((t & 31) == 0) ws[t >> 5] = s;
    __syncthreads();
    if (t == 0) *o = ws[0] + ws[1] + ws[2] + ws[3];
}

// ================= Kernel: kdd partials (16 j x 8 chunks) =================
__global__ void kdd_kernel(const float* __restrict__ dom) {
    int j = blockIdx.x, chunk = blockIdx.y;
    int warp = threadIdx.x >> 5, lane = threadIdx.x & 31;
    const float* dj = dom + (size_t)j * NM * FDIM;
    float acc = 0.f;
    int m0 = chunk * 8 + warp * 2;
    for (int m = m0; m < m0 + 2; m++) {
        float4 dm[4];
        #pragma unroll
        for (int q = 0; q < 4; q++)
            dm[q] = *(const float4*)&dj[(size_t)m * FDIM + q * 128 + (lane << 2)];
        float d2m = g_d2[j * NM + m];
        for (int n = 0; n < NM; n++) {
            float dot = 0.f;
            #pragma unroll
            for (int q = 0; q < 4; q++) {
                float4 dn = *(const float4*)&dj[(size_t)n * FDIM + q * 128 + (lane << 2)];
                dot += dm[q].x*dn.x + dm[q].y*dn.y + dm[q].z*dn.z + dm[q].w*dn.w;
            }
            #pragma unroll
            for (int off = 16; off; off >>= 1) dot += __shfl_xor_sync(0xffffffffu, dot, off);
            acc += expf(-2.f * (d2m + g_d2[j * NM + n] - 2.f * dot));
        }
    }
    __shared__ float ws[4];
    if (lane == 0) ws[warp] = acc;
    __syncthreads();
    if (threadIdx.x == 0) g_kddp[j * 8 + chunk] = ws[0] + ws[1] + ws[2] + ws[3];
}

// ================= GEMM1: K_hd = exp(4*h.domT - 2*(h2+d2)), bf16 out ========
// 128x128x64 tiles, 256 threads, warp layout 2m x 4n (warp tile 64x32)
__global__ void __launch_bounds__(256, 1) gemm1_kernel() {
    extern __shared__ char smem[];
    const int tid = threadIdx.x;
    const int lane = tid & 31, wid = tid >> 5;
    const int wm = (wid >> 2) * 64;
    const int wn = (wid & 3) * 32;
    const int m0 = blockIdx.y * 128;
    const int n0 = blockIdx.x * 128;

    uint32_t As_base = (uint32_t)__cvta_generic_to_shared(smem);
    uint32_t Bs_base = As_base + 32768;

    float acc[4][4][4] = {};

    auto load_stage = [&](int ki, int s) {
        const __nv_bfloat16* ha = g_hb + (size_t)m0 * FDIM + ki * 64;
        const __nv_bfloat16* da = g_db + (size_t)n0 * FDIM + ki * 64;
        uint32_t a_s = As_base + s * 16384;
        uint32_t b_s = Bs_base + s * 16384;
        #pragma unroll
        for (int i = 0; i < 4; i++) {
            int lin = tid + i * 256;
            int r = lin >> 3, c = lin & 7;
            uint32_t off = (uint32_t)(r * 128 + ((c ^ (r & 7)) << 4));
            cp16(a_s + off, ha + (size_t)r * FDIM + c * 8);
            cp16(b_s + off, da + (size_t)r * FDIM + c * 8);
        }
        cp_commit();
    };

    auto compute = [&](int s) {
        uint32_t a_s = As_base + s * 16384;
        uint32_t b_s = Bs_base + s * 16384;
        const int rlo = lane & 15, chi = lane >> 4;
        #pragma unroll
        for (int kk = 0; kk < 4; kk++) {
            uint32_t a[4][4], b[2][4];
            #pragma unroll
            for (int im = 0; im < 4; im++) {
                int row = wm + im * 16 + rlo;
                int ch = kk * 2 + chi;
                ldm_x4(a[im], a_s + row * 128 + ((ch ^ (row & 7)) << 4));
            }
            #pragma unroll
            for (int ib = 0; ib < 2; ib++) {
                int row = wn + ib * 16 + rlo;
                int ch = kk * 2 + chi;
                ldm_x4(b[ib], b_s + row * 128 + ((ch ^ (row & 7)) << 4));
            }
            #pragma unroll
            for (int im = 0; im < 4; im++) {
                mma_bf16(acc[im][0], a[im], b[0][0], b[0][2]);
                mma_bf16(acc[im][1], a[im], b[0][1], b[0][3]);
                mma_bf16(acc[im][2], a[im], b[1][0], b[1][2]);
                mma_bf16(acc[im][3], a[im], b[1][1], b[1][3]);
            }
        }
    };

    load_stage(0, 0);
    for (int ki = 0; ki < 8; ki++) {
        int cur = ki & 1;
        if (ki + 1 < 8) { load_stage(ki + 1, cur ^ 1); cp_wait<1>(); }
        else            { cp_wait<0>(); }
        __syncthreads();
        compute(cur);
        __syncthreads();
    }

    // epilogue
    const int qr = lane >> 2;
    const int qc = (lane & 3) * 2;
    #pragma unroll
    for (int im = 0; im < 4; im++) {
        int r0g = m0 + wm + im * 16 + qr;
        float h2a = g_h2[r0g], h2b = g_h2[r0g + 8];
        #pragma unroll
        for (int in = 0; in < 4; in++) {
            int cg = n0 + wn + in * 8 + qc;
            float d2x = g_d2[cg], d2y = g_d2[cg + 1];
            float* c = acc[im][in];
            __nv_bfloat162 v0 = __floats2bfloat162_rn(
                expf(4.f * c[0] - 2.f * (h2a + d2x)),
                expf(4.f * c[1] - 2.f * (h2a + d2y)));
            __nv_bfloat162 v1 = __floats2bfloat162_rn(
                expf(4.f * c[2] - 2.f * (h2b + d2x)),
                expf(4.f * c[3] - 2.f * (h2b + d2y)));
            *(__nv_bfloat162*)&g_Khd[(size_t)r0g * JM + cg] = v0;
            *(__nv_bfloat162*)&g_Khd[(size_t)(r0g + 8) * JM + cg] = v1;
        }
    }
}

// ================= Kernel: per-row softmax over domains =================
__global__ void prob_kernel() {
    int row = (int)((blockIdx.x * blockDim.x + threadIdx.x) >> 5);
    int lane = threadIdx.x & 31;
    if (row >= BATCH) return;
    const __nv_bfloat162* r = (const __nv_bfloat162*)(g_Khd + (size_t)row * JM);
    float e[NJ];
    float mx = -1e30f;
    #pragma unroll
    for (int j = 0; j < NJ; j++) {
        __nv_bfloat162 v = r[j * 32 + lane];
        float s = __bfloat162float(v.x) + __bfloat162float(v.y);
        #pragma unroll
        for (int off = 16; off; off >>= 1) s += __shfl_xor_sync(0xffffffffu, s, off);
        float kdd = 0.f;
        #pragma unroll
        for (int c = 0; c < 8; c++) kdd += g_kddp[j * 8 + c];
        kdd *= (1.0f / (NM * NM));
        float mmd = 1.0f - s * (2.0f / 64.0f) + kdd;
        e[j] = -mmd;
        mx = fmaxf(mx, e[j]);
    }
    float den = 0.f;
    #pragma unroll
    for (int j = 0; j < NJ; j++) { e[j] = expf(e[j] - mx); den += e[j]; }
    float inv = 1.0f / den;
    if (lane == 0) {
        #pragma unroll
        for (int j = 0; j < NJ; j++) g_prob[row * NJ + j] = e[j] * inv;
    }
}

// ================= GEMM2: out = (prob .* Khd) @ W + prob @ bvec ==========
__global__ void __launch_bounds__(256, 1) gemm2_kernel(const float* __restrict__ bvec,
                                                       float* __restrict__ out) {
    extern __shared__ char smem[];
    __nv_bfloat16* As = (__nv_bfloat16*)smem;                   // 2 x 16KB
    float* sp         = (float*)(smem + 65536);                 // [128][16] 8KB
    __nv_bfloat16* Ae = (__nv_bfloat16*)(smem + 73728);         // [128][24] 6KB
    __nv_bfloat16* Be = (__nv_bfloat16*)(smem + 79872);         // [128][24] 6KB

    const int tid = threadIdx.x;
    const int lane = tid & 31, wid = tid >> 5;
    const int wm = (wid >> 2) * 64;
    const int wn = (wid & 3) * 32;
    const int m0 = blockIdx.y * 128;
    const int n0 = blockIdx.x * 128;

    uint32_t As_base = (uint32_t)__cvta_generic_to_shared(smem);
    uint32_t Bs_base = As_base + 32768;
    uint32_t Ae_base = As_base + 73728;
    uint32_t Be_base = As_base + 79872;

    // stage prob (fp32 + bf16) and bvec^T tiles
    for (int idx = tid; idx < 128 * 16; idx += 256) {
        int rr = idx >> 4, j = idx & 15;
        float p = g_prob[(size_t)(m0 + rr) * NJ + j];
        sp[rr * 16 + j] = p;
        Ae[rr * 24 + j] = __float2bfloat16(p);
        Be[rr * 24 + j] = __float2bfloat16(bvec[(size_t)j * NU + n0 + rr]);
    }
    __syncthreads();

    float acc[4][4][4] = {};
    uint4 areg[4];

    auto ldgA = [&](int ki) {
        const __nv_bfloat16* src = g_Khd + (size_t)m0 * JM + ki * 64;
        #pragma unroll
        for (int i = 0; i < 4; i++) {
            int lin = tid + i * 256;
            int r = lin >> 3, c = lin & 7;
            areg[i] = *(const uint4*)(src + (size_t)r * JM + c * 8);
        }
    };
    auto stsA = [&](int ki, int s) {
        __nv_bfloat16* dst = As + s * 8192;
        #pragma unroll
        for (int i = 0; i < 4; i++) {
            int lin = tid + i * 256;
            int r = lin >> 3, c = lin & 7;
            __nv_bfloat162 sc = __float2bfloat162_rn(sp[r * 16 + ki]);
            __nv_bfloat162* v = (__nv_bfloat162*)&areg[i];
            __nv_bfloat162 o0 = __hmul2(v[0], sc), o1 = __hmul2(v[1], sc);
            __nv_bfloat162 o2 = __hmul2(v[2], sc), o3 = __hmul2(v[3], sc);
            uint4 u;
            u.x = *(uint32_t*)&o0; u.y = *(uint32_t*)&o1;
            u.z = *(uint32_t*)&o2; u.w = *(uint32_t*)&o3;
            *(uint4*)((char*)dst + r * 128 + ((c ^ (r & 7)) << 4)) = u;
        }
    };
    auto ldB = [&](int ki, int s) {
        const __nv_bfloat16* src = g_Wb + (size_t)ki * 64 * NU + n0;
        uint32_t b_s = Bs_base + s * 16384;
        #pragma unroll
        for (int i = 0; i < 4; i++) {
            int lin = tid + i * 256;
            int r = lin >> 4, c = lin & 15;
            cp16(b_s + r * 256 + ((c ^ (r & 7)) << 4), src + (size_t)r * NU + c * 8);
        }
        cp_commit();
    };
    auto compute = [&](int s) {
        uint32_t a_s = As_base + s * 16384;
        uint32_t b_s = Bs_base + s * 16384;
        const int rlo = lane & 15, chi = lane >> 4;
        #pragma unroll
        for (int kk = 0; kk < 4; kk++) {
            uint32_t a[4][4], b[2][4];
            #pragma unroll
            for (int im = 0; im < 4; im++) {
                int row = wm + im * 16 + rlo;
                int ch = kk * 2 + chi;
                ldm_x4(a[im], a_s + row * 128 + ((ch ^ (row & 7)) << 4));
            }
            #pragma unroll
            for (int ib = 0; ib < 2; ib++) {
                int row = kk * 16 + rlo;                     // k index
                int ch = (wn + ib * 16) / 8 + chi;           // n 16B-chunk
                ldm_x4t(b[ib], b_s + row * 256 + ((ch ^ (row & 7)) << 4));
            }
            #pragma unroll
            for (int im = 0; im < 4; im++) {
                mma_bf16(acc[im][0], a[im], b[0][0], b[0][1]);
                mma_bf16(acc[im][1], a[im], b[0][2], b[0][3]);
                mma_bf16(acc[im][2], a[im], b[1][0], b[1][1]);
                mma_bf16(acc[im][3], a[im], b[1][2], b[1][3]);
            }
        }
    };

    ldgA(0); ldB(0, 0);
    for (int ki = 0; ki < 16; ki++) {
        int cur = ki & 1;
        stsA(ki, cur);
        if (ki + 1 < 16) { ldgA(ki + 1); ldB(ki + 1, cur ^ 1); cp_wait<1>(); }
        else             { cp_wait<0>(); }
        __syncthreads();
        compute(cur);
        __syncthreads();
    }

    // ---- bias fold: one extra k16 step with A'=prob, B'=bvec^T ----
    {
        const int rlo = lane & 15, chi = lane >> 4;
        uint32_t b[2][4];
        #pragma unroll
        for (int ib = 0; ib < 2; ib++) {
            int row = wn + ib * 16 + rlo;
            ldm_x4(b[ib], Be_base + row * 48 + chi * 16);
        }
        #pragma unroll
        for (int im = 0; im < 4; im++) {
            uint32_t a[4];
            int row = wm + im * 16 + rlo;
            ldm_x4(a, Ae_base + row * 48 + chi * 16);
            mma_bf16(acc[im][0], a, b[0][0], b[0][2]);
            mma_bf16(acc[im][1], a, b[0][1], b[0][3]);
            mma_bf16(acc[im][2], a, b[1][0], b[1][2]);
            mma_bf16(acc[im][3], a, b[1][1], b[1][3]);
        }
    }

    // epilogue
    const int qr = lane >> 2;
    const int qc = (lane & 3) * 2;
    #pragma unroll
    for (int im = 0; im < 4; im++) {
        int r0g = m0 + wm + im * 16 + qr;
        #pragma unroll
        for (int in = 0; in < 4; in++) {
            int cg = n0 + wn + in * 8 + qc;
            float* c = acc[im][in];
            float2 v0 = {c[0], c[1]}, v1 = {c[2], c[3]};
            *(float2*)&out[(size_t)r0g * NU + cg] = v0;
            *(float2*)&out[(size_t)(r0g + 8) * NU + cg] = v1;
        }
    }
}

// ============================================================
extern "C" void kernel_launch(void* const* d_in, const int* in_sizes, int n_in,
                              void* d_out, int out_size) {
    const float* h    = (const float*)d_in[0];   // [B, F]
    const float* dom  = (const float*)d_in[1];   // [J, M, F]
    const float* W    = (const float*)d_in[2];   // [J, M, U]
    const float* bvec = (const float*)d_in[3];   // [J, U]
    float* out = (float*)d_out;                  // [B, U]

    cudaFuncSetAttribute(gemm1_kernel, cudaFuncAttributeMaxDynamicSharedMemorySize, 65536);
    cudaFuncSetAttribute(gemm2_kernel, cudaFuncAttributeMaxDynamicSharedMemorySize, 86016);

    convert_kernel<<<1536, 256>>>(h, dom, W);
    sumsq_kernel<<<BATCH + JM, 128>>>(h, dom);
    kdd_kernel<<<dim3(NJ, 8), 128>>>(dom);
    gemm1_kernel<<<dim3(JM / 128, BATCH / 128), 256, 65536>>>();
    prob_kernel<<<(BATCH * 32) / 256, 256>>>();
    gemm2_kernel<<<dim3(NU / 128, BATCH / 128), 256, 86016>>>(bvec, out);
}

// round 3
// speedup vs baseline: 4.5291x; 1.0170x over previous
#include <cuda_runtime.h>
#include <cuda_bf16.h>
#include <math.h>
#include <stdint.h>

#define BATCH 4096
#define FDIM  512
#define NJ    16
#define NM    64
#define NU    512
#define JM    (NJ*NM)   // 1024

// ---- scratch (device globals; no allocation allowed) ----
__device__ __nv_bfloat16 g_hb[(size_t)BATCH * FDIM];   // 4 MB
__device__ __nv_bfloat16 g_db[(size_t)JM * FDIM];      // 1 MB
__device__ __nv_bfloat16 g_Wb[(size_t)JM * NU];        // 1 MB
__device__ __nv_bfloat16 g_Khd[(size_t)BATCH * JM];    // 8 MB
__device__ float g_h2[BATCH];
__device__ float g_d2[JM];
__device__ float g_kddp[NJ * 8];
__device__ float g_jsum[BATCH * NJ];
__device__ float g_prob[BATCH * NJ];

// ================= PTX helpers =================
__device__ __forceinline__ void cp16(uint32_t dst, const void* src) {
    asm volatile("cp.async.cg.shared.global [%0], [%1], 16;\n" :: "r"(dst), "l"(src));
}
__device__ __forceinline__ void cp_commit() { asm volatile("cp.async.commit_group;\n"); }
template <int N> __device__ __forceinline__ void cp_wait() {
    asm volatile("cp.async.wait_group %0;\n" :: "n"(N));
}
__device__ __forceinline__ void ldm_x4(uint32_t a[4], uint32_t addr) {
    asm volatile("ldmatrix.sync.aligned.m8n8.x4.shared.b16 {%0,%1,%2,%3}, [%4];\n"
                 : "=r"(a[0]), "=r"(a[1]), "=r"(a[2]), "=r"(a[3]) : "r"(addr));
}
__device__ __forceinline__ void ldm_x4t(uint32_t a[4], uint32_t addr) {
    asm volatile("ldmatrix.sync.aligned.m8n8.x4.trans.shared.b16 {%0,%1,%2,%3}, [%4];\n"
                 : "=r"(a[0]), "=r"(a[1]), "=r"(a[2]), "=r"(a[3]) : "r"(addr));
}
__device__ __forceinline__ void mma_bf16(float c[4], const uint32_t a[4], uint32_t b0, uint32_t b1) {
    asm volatile(
        "mma.sync.aligned.m16n8k16.row.col.f32.bf16.bf16.f32 "
        "{%0,%1,%2,%3}, {%4,%5,%6,%7}, {%8,%9}, {%0,%1,%2,%3};\n"
        : "+f"(c[0]), "+f"(c[1]), "+f"(c[2]), "+f"(c[3])
        : "r"(a[0]), "r"(a[1]), "r"(a[2]), "r"(a[3]), "r"(b0), "r"(b1));
}

// ================= prep: convert to bf16 + row sumsq + zero jsum =========
// blocks [0, B+JM): h/dom rows (convert + sumsq). blocks [B+JM, B+2JM): W rows.
__global__ void prep_kernel(const float* __restrict__ h,
                            const float* __restrict__ dom,
                            const float* __restrict__ W) {
    int r = blockIdx.x;
    int t = threadIdx.x;            // 128 threads, 4 floats each
    if (r < BATCH + JM) {
        const float* p;
        __nv_bfloat16* dst;
        float* o;
        if (r < BATCH) { p = h + (size_t)r * FDIM; dst = g_hb + (size_t)r * FDIM; o = &g_h2[r]; }
        else { p = dom + (size_t)(r - BATCH) * FDIM; dst = g_db + (size_t)(r - BATCH) * FDIM; o = &g_d2[r - BATCH]; }
        float4 v = *(const float4*)&p[t << 2];
        __nv_bfloat162 o0 = __floats2bfloat162_rn(v.x, v.y);
        __nv_bfloat162 o1 = __floats2bfloat162_rn(v.z, v.w);
        uint2 u; u.x = *(uint32_t*)&o0; u.y = *(uint32_t*)&o1;
        *(uint2*)&dst[t << 2] = u;
        float s = v.x*v.x + v.y*v.y + v.z*v.z + v.w*v.w;
        #pragma unroll
        for (int off = 16; off; off >>= 1) s += __shfl_xor_sync(0xffffffffu, s, off);
        __shared__ float ws[4];
        if ((t & 31) == 0) ws[t >> 5] = s;
        if (r < BATCH && t < NJ) g_jsum[r * NJ + t] = 0.f;
        __syncthreads();
        if (t == 0) *o = ws[0] + ws[1] + ws[2] + ws[3];
    } else {
        int wr = r - BATCH - JM;
        const float* p = W + (size_t)wr * NU;
        float4 v = *(const float4*)&p[t << 2];
        __nv_bfloat162 o0 = __floats2bfloat162_rn(v.x, v.y);
        __nv_bfloat162 o1 = __floats2bfloat162_rn(v.z, v.w);
        uint2 u; u.x = *(uint32_t*)&o0; u.y = *(uint32_t*)&o1;
        *(uint2*)&g_Wb[(size_t)wr * NU + (t << 2)] = u;
    }
}

// ================= kdd partials (16 j x 8 chunks) =================
__global__ void kdd_kernel(const float* __restrict__ dom) {
    int j = blockIdx.x, chunk = blockIdx.y;
    int warp = threadIdx.x >> 5, lane = threadIdx.x & 31;
    const float* dj = dom + (size_t)j * NM * FDIM;
    float acc = 0.f;
    int m0 = chunk * 8 + warp * 2;
    for (int m = m0; m < m0 + 2; m++) {
        float4 dm[4];
        #pragma unroll
        for (int q = 0; q < 4; q++)
            dm[q] = *(const float4*)&dj[(size_t)m * FDIM + q * 128 + (lane << 2)];
        float d2m = g_d2[j * NM + m];
        for (int n = 0; n < NM; n++) {
            float dot = 0.f;
            #pragma unroll
            for (int q = 0; q < 4; q++) {
                float4 dn = *(const float4*)&dj[(size_t)n * FDIM + q * 128 + (lane << 2)];
                dot += dm[q].x*dn.x + dm[q].y*dn.y + dm[q].z*dn.z + dm[q].w*dn.w;
            }
            #pragma unroll
            for (int off = 16; off; off >>= 1) dot += __shfl_xor_sync(0xffffffffu, dot, off);
            acc += expf(-2.f * (d2m + g_d2[j * NM + n] - 2.f * dot));
        }
    }
    __shared__ float ws[4];
    if (lane == 0) ws[warp] = acc;
    __syncthreads();
    if (threadIdx.x == 0) g_kddp[j * 8 + chunk] = ws[0] + ws[1] + ws[2] + ws[3];
}

// ================= GEMM1: Khd = exp(4*h.domT - 2*(h2+d2)), bf16 out ========
// 128x128 tile, BK=32, 3-stage cp.async, 256 threads, 2 CTAs/SM.
// Also accumulates per-(row, j) sums of exp into g_jsum via atomics.
__global__ void __launch_bounds__(256, 2) gemm1_kernel() {
    extern __shared__ char smem[];
    const int tid = threadIdx.x;
    const int lane = tid & 31, wid = tid >> 5;
    const int wm = (wid >> 2) * 64;     // 2 m warps
    const int wn = (wid & 3) * 32;      // 4 n warps
    const int m0 = blockIdx.y * 128;
    const int n0 = blockIdx.x * 128;

    uint32_t base = (uint32_t)__cvta_generic_to_shared(smem);

    const int rlo = lane & 15, chi = lane >> 4;
    int arow[4], asw[4], brow[2], bsw[2];
    #pragma unroll
    for (int im = 0; im < 4; im++) { arow[im] = wm + im * 16 + rlo; asw[im] = (arow[im] >> 1) & 3; }
    #pragma unroll
    for (int ib = 0; ib < 2; ib++) { brow[ib] = wn + ib * 16 + rlo; bsw[ib] = (brow[ib] >> 1) & 3; }

    float acc[4][4][4] = {};

    auto load_stage = [&](int ki, int s) {
        const __nv_bfloat16* ha = g_hb + (size_t)m0 * FDIM + ki * 32;
        const __nv_bfloat16* da = g_db + (size_t)n0 * FDIM + ki * 32;
        uint32_t a_s = base + s * 16384;
        uint32_t b_s = a_s + 8192;
        #pragma unroll
        for (int i = 0; i < 2; i++) {
            int lin = tid + i * 256;
            int r = lin >> 2, c = lin & 3;
            uint32_t off = (uint32_t)(r * 64 + (((c ^ ((r >> 1) & 3))) << 4));
            cp16(a_s + off, ha + (size_t)r * FDIM + c * 8);
            cp16(b_s + off, da + (size_t)r * FDIM + c * 8);
        }
        cp_commit();
    };

    auto compute = [&](int s) {
        uint32_t a_s = base + s * 16384;
        uint32_t b_s = a_s + 8192;
        #pragma unroll
        for (int kk = 0; kk < 2; kk++) {
            int ch = kk * 2 + chi;
            uint32_t a[4][4], b[2][4];
            #pragma unroll
            for (int im = 0; im < 4; im++)
                ldm_x4(a[im], a_s + arow[im] * 64 + ((ch ^ asw[im]) << 4));
            #pragma unroll
            for (int ib = 0; ib < 2; ib++)
                ldm_x4(b[ib], b_s + brow[ib] * 64 + ((ch ^ bsw[ib]) << 4));
            #pragma unroll
            for (int im = 0; im < 4; im++) {
                mma_bf16(acc[im][0], a[im], b[0][0], b[0][2]);
                mma_bf16(acc[im][1], a[im], b[0][1], b[0][3]);
                mma_bf16(acc[im][2], a[im], b[1][0], b[1][2]);
                mma_bf16(acc[im][3], a[im], b[1][1], b[1][3]);
            }
        }
    };

    load_stage(0, 0);
    load_stage(1, 1);
    #pragma unroll 1
    for (int ki = 0; ki < 16; ki++) {
        if (ki < 15) cp_wait<1>(); else cp_wait<0>();
        __syncthreads();
        if (ki + 2 < 16) load_stage(ki + 2, (ki + 2) % 3);
        compute(ki % 3);
    }

    // epilogue: exp, bf16 store, and per-(row, j) partial sums
    const int qr = lane >> 2;
    const int qc = (lane & 3) * 2;
    const int jg = (n0 + wn) >> 6;   // global j for this warp's 32-col band
    #pragma unroll
    for (int im = 0; im < 4; im++) {
        int r0g = m0 + wm + im * 16 + qr;
        float h2a = g_h2[r0g], h2b = g_h2[r0g + 8];
        float rs0 = 0.f, rs1 = 0.f;
        #pragma unroll
        for (int in = 0; in < 4; in++) {
            int cg = n0 + wn + in * 8 + qc;
            float d2x = g_d2[cg], d2y = g_d2[cg + 1];
            float* c = acc[im][in];
            float e00 = expf(4.f * c[0] - 2.f * (h2a + d2x));
            float e01 = expf(4.f * c[1] - 2.f * (h2a + d2y));
            float e10 = expf(4.f * c[2] - 2.f * (h2b + d2x));
            float e11 = expf(4.f * c[3] - 2.f * (h2b + d2y));
            rs0 += e00 + e01;
            rs1 += e10 + e11;
            *(__nv_bfloat162*)&g_Khd[(size_t)r0g * JM + cg] = __floats2bfloat162_rn(e00, e01);
            *(__nv_bfloat162*)&g_Khd[(size_t)(r0g + 8) * JM + cg] = __floats2bfloat162_rn(e10, e11);
        }
        rs0 += __shfl_xor_sync(0xffffffffu, rs0, 1);
        rs0 += __shfl_xor_sync(0xffffffffu, rs0, 2);
        rs1 += __shfl_xor_sync(0xffffffffu, rs1, 1);
        rs1 += __shfl_xor_sync(0xffffffffu, rs1, 2);
        if ((lane & 3) == 0) {
            atomicAdd(&g_jsum[r0g * NJ + jg], rs0);
            atomicAdd(&g_jsum[(r0g + 8) * NJ + jg], rs1);
        }
    }
}

// ================= prob: softmax over domains from jsum =================
__global__ void prob_kernel() {
    __shared__ float kddm[NJ];
    int t = threadIdx.x;
    if (t < NJ) {
        float s = 0.f;
        #pragma unroll
        for (int c = 0; c < 8; c++) s += g_kddp[t * 8 + c];
        kddm[t] = s * (1.0f / (NM * NM));
    }
    __syncthreads();
    int row = blockIdx.x * 256 + t;
    float e[NJ];
    float mx = -1e30f;
    #pragma unroll
    for (int j = 0; j < NJ; j++) {
        float s = g_jsum[row * NJ + j];
        float mmd = 1.0f - s * (2.0f / 64.0f) + kddm[j];
        e[j] = -mmd;
        mx = fmaxf(mx, e[j]);
    }
    float den = 0.f;
    #pragma unroll
    for (int j = 0; j < NJ; j++) { e[j] = expf(e[j] - mx); den += e[j]; }
    float inv = 1.0f / den;
    #pragma unroll
    for (int j = 0; j < NJ; j++) g_prob[row * NJ + j] = e[j] * inv;
}

// ================= GEMM2: out = (prob .* Khd) @ W + prob @ bvec ==========
// 128x128 tile, BK=64, 512 threads (4x4 warps, warp tile 32x32),
// A: LDG+scale+STS double buffer; B: cp.async 3-stage ring.
__global__ void __launch_bounds__(512, 1) gemm2_kernel(const float* __restrict__ bvec,
                                                       float* __restrict__ out) {
    extern __shared__ char smem[];
    __nv_bfloat16* As = (__nv_bfloat16*)smem;          // 2 x 16KB at 0
    float* sp         = (float*)(smem + 81920);        // [128][16] 8KB
    const int tid = threadIdx.x;
    const int lane = tid & 31, wid = tid >> 5;
    const int wm = (wid >> 2) * 32;
    const int wn = (wid & 3) * 32;
    const int m0 = blockIdx.y * 128;
    const int n0 = blockIdx.x * 128;

    uint32_t base = (uint32_t)__cvta_generic_to_shared(smem);
    uint32_t Bs_base = base + 32768;                   // 3 x 16KB
    uint32_t Ae_base = base + 90112;                   // [128][24] bf16 6KB
    uint32_t Be_base = base + 96256;                   // [128][24] bf16 6KB
    __nv_bfloat16* Ae = (__nv_bfloat16*)(smem + 90112);
    __nv_bfloat16* Be = (__nv_bfloat16*)(smem + 96256);

    // stage prob (fp32 + bf16) and bvec^T
    for (int idx = tid; idx < 128 * 16; idx += 512) {
        int rr = idx >> 4, j = idx & 15;
        float p = g_prob[(size_t)(m0 + rr) * NJ + j];
        sp[rr * 16 + j] = p;
        Ae[rr * 24 + j] = __float2bfloat16(p);
        Be[rr * 24 + j] = __float2bfloat16(bvec[(size_t)j * NU + n0 + rr]);
    }

    float acc[2][4][4] = {};
    uint4 areg[2];

    auto ldgA = [&](int ki) {
        const __nv_bfloat16* src = g_Khd + (size_t)m0 * JM + ki * 64;
        #pragma unroll
        for (int i = 0; i < 2; i++) {
            int lin = tid + i * 512;
            int r = lin >> 3, c = lin & 7;
            areg[i] = *(const uint4*)(src + (size_t)r * JM + c * 8);
        }
    };
    auto stsA = [&](int ki, int s) {
        char* dst = (char*)As + s * 16384;
        #pragma unroll
        for (int i = 0; i < 2; i++) {
            int lin = tid + i * 512;
            int r = lin >> 3, c = lin & 7;
            __nv_bfloat162 sc = __float2bfloat162_rn(sp[r * 16 + ki]);
            __nv_bfloat162* v = (__nv_bfloat162*)&areg[i];
            __nv_bfloat162 o0 = __hmul2(v[0], sc), o1 = __hmul2(v[1], sc);
            __nv_bfloat162 o2 = __hmul2(v[2], sc), o3 = __hmul2(v[3], sc);
            uint4 u;
            u.x = *(uint32_t*)&o0; u.y = *(uint32_t*)&o1;
            u.z = *(uint32_t*)&o2; u.w = *(uint32_t*)&o3;
            *(uint4*)(dst + r * 128 + ((c ^ (r & 7)) << 4)) = u;
        }
    };
    auto ldB = [&](int ki, int s) {
        const __nv_bfloat16* src = g_Wb + (size_t)ki * 64 * NU + n0;
        uint32_t b_s = Bs_base + s * 16384;
        #pragma unroll
        for (int i = 0; i < 2; i++) {
            int lin = tid + i * 512;
            int r = lin >> 4, c = lin & 15;
            cp16(b_s + r * 256 + ((c ^ (r & 7)) << 4), src + (size_t)r * NU + c * 8);
        }
        cp_commit();
    };

    const int rlo = lane & 15, chi = lane >> 4;
    auto compute = [&](int sa, int sb) {
        uint32_t a_s = base + sa * 16384;
        uint32_t b_s = Bs_base + sb * 16384;
        #pragma unroll
        for (int kk = 0; kk < 4; kk++) {
            uint32_t a[2][4], b[2][4];
            #pragma unroll
            for (int im = 0; im < 2; im++) {
                int row = wm + im * 16 + rlo;
                int ch = kk * 2 + chi;
                ldm_x4(a[im], a_s + row * 128 + ((ch ^ (row & 7)) << 4));
            }
            #pragma unroll
            for (int ib = 0; ib < 2; ib++) {
                int row = kk * 16 + rlo;
                int ch = (wn >> 3) + ib * 2 + chi;
                ldm_x4t(b[ib], b_s + row * 256 + ((ch ^ (row & 7)) << 4));
            }
            #pragma unroll
            for (int im = 0; im < 2; im++) {
                mma_bf16(acc[im][0], a[im], b[0][0], b[0][1]);
                mma_bf16(acc[im][1], a[im], b[0][2], b[0][3]);
                mma_bf16(acc[im][2], a[im], b[1][0], b[1][1]);
                mma_bf16(acc[im][3], a[im], b[1][2], b[1][3]);
            }
        }
    };

    ldgA(0);
    ldB(0, 0);
    ldB(1, 1);
    #pragma unroll 1
    for (int ki = 0; ki < 16; ki++) {
        stsA(ki, ki & 1);
        if (ki + 1 < 16) ldgA(ki + 1);
        if (ki < 15) cp_wait<1>(); else cp_wait<0>();
        __syncthreads();
        if (ki + 2 < 16) ldB(ki + 2, (ki + 2) % 3);
        compute(ki & 1, ki % 3);
        __syncthreads();
    }

    // ---- bias fold: one extra k16 step with A'=prob, B'=bvec^T ----
    {
        uint32_t b[2][4];
        #pragma unroll
        for (int ib = 0; ib < 2; ib++) {
            int row = wn + ib * 16 + rlo;
            ldm_x4(b[ib], Be_base + row * 48 + chi * 16);
        }
        #pragma unroll
        for (int im = 0; im < 2; im++) {
            uint32_t a[4];
            int row = wm + im * 16 + rlo;
            ldm_x4(a, Ae_base + row * 48 + chi * 16);
            mma_bf16(acc[im][0], a, b[0][0], b[0][2]);
            mma_bf16(acc[im][1], a, b[0][1], b[0][3]);
            mma_bf16(acc[im][2], a, b[1][0], b[1][2]);
            mma_bf16(acc[im][3], a, b[1][1], b[1][3]);
        }
    }

    // epilogue
    const int qr = lane >> 2;
    const int qc = (lane & 3) * 2;
    #pragma unroll
    for (int im = 0; im < 2; im++) {
        int r0g = m0 + wm + im * 16 + qr;
        #pragma unroll
        for (int in = 0; in < 4; in++) {
            int cg = n0 + wn + in * 8 + qc;
            float* c = acc[im][in];
            float2 v0 = {c[0], c[1]}, v1 = {c[2], c[3]};
            *(float2*)&out[(size_t)r0g * NU + cg] = v0;
            *(float2*)&out[(size_t)(r0g + 8) * NU + cg] = v1;
        }
    }
}

// ============================================================
extern "C" void kernel_launch(void* const* d_in, const int* in_sizes, int n_in,
                              void* d_out, int out_size) {
    const float* h    = (const float*)d_in[0];   // [B, F]
    const float* dom  = (const float*)d_in[1];   // [J, M, F]
    const float* W    = (const float*)d_in[2];   // [J, M, U]
    const float* bvec = (const float*)d_in[3];   // [J, U]
    float* out = (float*)d_out;                  // [B, U]

    cudaFuncSetAttribute(gemm1_kernel, cudaFuncAttributeMaxDynamicSharedMemorySize, 49152);
    cudaFuncSetAttribute(gemm2_kernel, cudaFuncAttributeMaxDynamicSharedMemorySize, 102400);

    prep_kernel<<<BATCH + 2 * JM, 128>>>(h, dom, W);
    kdd_kernel<<<dim3(NJ, 8), 128>>>(dom);
    gemm1_kernel<<<dim3(JM / 128, BATCH / 128), 256, 49152>>>();
    prob_kernel<<<BATCH / 256, 256>>>();
    gemm2_kernel<<<dim3(NU / 128, BATCH / 128), 512, 102400>>>(bvec, out);
}

// round 4
// speedup vs baseline: 4.6540x; 1.0276x over previous
#include <cuda_runtime.h>
#include <cuda_bf16.h>
#include <math.h>
#include <stdint.h>

#define BATCH 4096
#define FDIM  512
#define NJ    16
#define NM    64
#define NU    512
#define JM    (NJ*NM)   // 1024

// ---- scratch (device globals; no allocation allowed) ----
__device__ __nv_bfloat16 g_hb[(size_t)BATCH * FDIM];   // 4 MB
__device__ __nv_bfloat16 g_db[(size_t)JM * FDIM];      // 1 MB
__device__ __nv_bfloat16 g_Wb[(size_t)JM * NU];        // 1 MB
__device__ __nv_bfloat16 g_A2[(size_t)BATCH * JM];     // 8 MB : e-scaled Khd
__device__ float g_h2[BATCH];
__device__ float g_d2[JM];
__device__ float g_kddp[NJ * 8];
__device__ float g_e[BATCH * NJ];
__device__ float g_Z[BATCH];

// ================= PTX helpers =================
__device__ __forceinline__ void cp16(uint32_t dst, const void* src) {
    asm volatile("cp.async.cg.shared.global [%0], [%1], 16;\n" :: "r"(dst), "l"(src));
}
__device__ __forceinline__ void cp_commit() { asm volatile("cp.async.commit_group;\n"); }
template <int N> __device__ __forceinline__ void cp_wait() {
    asm volatile("cp.async.wait_group %0;\n" :: "n"(N));
}
__device__ __forceinline__ void ldm_x4(uint32_t a[4], uint32_t addr) {
    asm volatile("ldmatrix.sync.aligned.m8n8.x4.shared.b16 {%0,%1,%2,%3}, [%4];\n"
                 : "=r"(a[0]), "=r"(a[1]), "=r"(a[2]), "=r"(a[3]) : "r"(addr));
}
__device__ __forceinline__ void ldm_x4t(uint32_t a[4], uint32_t addr) {
    asm volatile("ldmatrix.sync.aligned.m8n8.x4.trans.shared.b16 {%0,%1,%2,%3}, [%4];\n"
                 : "=r"(a[0]), "=r"(a[1]), "=r"(a[2]), "=r"(a[3]) : "r"(addr));
}
__device__ __forceinline__ void mma_bf16(float c[4], const uint32_t a[4], uint32_t b0, uint32_t b1) {
    asm volatile(
        "mma.sync.aligned.m16n8k16.row.col.f32.bf16.bf16.f32 "
        "{%0,%1,%2,%3}, {%4,%5,%6,%7}, {%8,%9}, {%0,%1,%2,%3};\n"
        : "+f"(c[0]), "+f"(c[1]), "+f"(c[2]), "+f"(c[3])
        : "r"(a[0]), "r"(a[1]), "r"(a[2]), "r"(a[3]), "r"(b0), "r"(b1));
}

// ================= prep: bf16 convert + row sumsq + zero Z ===============
__global__ void prep_kernel(const float* __restrict__ h,
                            const float* __restrict__ dom,
                            const float* __restrict__ W) {
    int r = blockIdx.x;
    int t = threadIdx.x;            // 128 threads, 4 floats each
    if (r < BATCH + JM) {
        const float* p;
        __nv_bfloat16* dst;
        float* o;
        if (r < BATCH) { p = h + (size_t)r * FDIM; dst = g_hb + (size_t)r * FDIM; o = &g_h2[r]; }
        else { p = dom + (size_t)(r - BATCH) * FDIM; dst = g_db + (size_t)(r - BATCH) * FDIM; o = &g_d2[r - BATCH]; }
        float4 v = *(const float4*)&p[t << 2];
        __nv_bfloat162 o0 = __floats2bfloat162_rn(v.x, v.y);
        __nv_bfloat162 o1 = __floats2bfloat162_rn(v.z, v.w);
        uint2 u; u.x = *(uint32_t*)&o0; u.y = *(uint32_t*)&o1;
        *(uint2*)&dst[t << 2] = u;
        float s = v.x*v.x + v.y*v.y + v.z*v.z + v.w*v.w;
        #pragma unroll
        for (int off = 16; off; off >>= 1) s += __shfl_xor_sync(0xffffffffu, s, off);
        __shared__ float ws[4];
        if ((t & 31) == 0) ws[t >> 5] = s;
        if (r < BATCH && t == 0) g_Z[r] = 0.f;
        __syncthreads();
        if (t == 0) *o = ws[0] + ws[1] + ws[2] + ws[3];
    } else {
        int wr = r - BATCH - JM;
        const float* p = W + (size_t)wr * NU;
        float4 v = *(const float4*)&p[t << 2];
        __nv_bfloat162 o0 = __floats2bfloat162_rn(v.x, v.y);
        __nv_bfloat162 o1 = __floats2bfloat162_rn(v.z, v.w);
        uint2 u; u.x = *(uint32_t*)&o0; u.y = *(uint32_t*)&o1;
        *(uint2*)&g_Wb[(size_t)wr * NU + (t << 2)] = u;
    }
}

// ================= kdd partials (16 j x 8 chunks) =================
__global__ void kdd_kernel(const float* __restrict__ dom) {
    int j = blockIdx.x, chunk = blockIdx.y;
    int warp = threadIdx.x >> 5, lane = threadIdx.x & 31;
    const float* dj = dom + (size_t)j * NM * FDIM;
    float acc = 0.f;
    int m0 = chunk * 8 + warp * 2;
    for (int m = m0; m < m0 + 2; m++) {
        float4 dm[4];
        #pragma unroll
        for (int q = 0; q < 4; q++)
            dm[q] = *(const float4*)&dj[(size_t)m * FDIM + q * 128 + (lane << 2)];
        float d2m = g_d2[j * NM + m];
        for (int n = 0; n < NM; n++) {
            float dot = 0.f;
            #pragma unroll
            for (int q = 0; q < 4; q++) {
                float4 dn = *(const float4*)&dj[(size_t)n * FDIM + q * 128 + (lane << 2)];
                dot += dm[q].x*dn.x + dm[q].y*dn.y + dm[q].z*dn.z + dm[q].w*dn.w;
            }
            #pragma unroll
            for (int off = 16; off; off >>= 1) dot += __shfl_xor_sync(0xffffffffu, dot, off);
            acc += expf(-2.f * (d2m + g_d2[j * NM + n] - 2.f * dot));
        }
    }
    __shared__ float ws[4];
    if (lane == 0) ws[warp] = acc;
    __syncthreads();
    if (threadIdx.x == 0) g_kddp[j * 8 + chunk] = ws[0] + ws[1] + ws[2] + ws[3];
}

// ================= GEMM1: A2 = e * exp(4*h.domT - 2*(h2+d2)) =============
// 128x128 tile (=2 full domains), BK=32, 3-stage, 256 thr, 2 CTAs/SM.
// Epilogue computes e[b,j]=exp(-mmd) in-block, scales, accumulates Z.
__global__ void __launch_bounds__(256, 2) gemm1_kernel() {
    extern __shared__ char smem[];
    __shared__ float jp[128][2];
    __shared__ float es[128][2];
    __shared__ float kddm[2];
    const int tid = threadIdx.x;
    const int lane = tid & 31, wid = tid >> 5;
    const int wm = (wid >> 2) * 64;     // 2 m warps
    const int wn = (wid & 3) * 32;      // 4 n warps
    const int m0 = blockIdx.y * 128;
    const int n0 = blockIdx.x * 128;
    const int j0 = blockIdx.x * 2;

    uint32_t base = (uint32_t)__cvta_generic_to_shared(smem);

    // init epilogue smem
    if (tid < 256) { jp[tid >> 1][tid & 1] = 0.f; }
    if (tid < 2) {
        float s = 0.f;
        #pragma unroll
        for (int c = 0; c < 8; c++) s += g_kddp[(j0 + tid) * 8 + c];
        kddm[tid] = s * (1.0f / (NM * NM));
    }

    const int rlo = lane & 15, chi = lane >> 4;
    int arow[4], asw[4], brow[2], bsw[2];
    #pragma unroll
    for (int im = 0; im < 4; im++) { arow[im] = wm + im * 16 + rlo; asw[im] = (arow[im] >> 1) & 3; }
    #pragma unroll
    for (int ib = 0; ib < 2; ib++) { brow[ib] = wn + ib * 16 + rlo; bsw[ib] = (brow[ib] >> 1) & 3; }

    float acc[4][4][4] = {};

    auto load_stage = [&](int ki, int s) {
        const __nv_bfloat16* ha = g_hb + (size_t)m0 * FDIM + ki * 32;
        const __nv_bfloat16* da = g_db + (size_t)n0 * FDIM + ki * 32;
        uint32_t a_s = base + s * 16384;
        uint32_t b_s = a_s + 8192;
        #pragma unroll
        for (int i = 0; i < 2; i++) {
            int lin = tid + i * 256;
            int r = lin >> 2, c = lin & 3;
            uint32_t off = (uint32_t)(r * 64 + (((c ^ ((r >> 1) & 3))) << 4));
            cp16(a_s + off, ha + (size_t)r * FDIM + c * 8);
            cp16(b_s + off, da + (size_t)r * FDIM + c * 8);
        }
        cp_commit();
    };

    auto compute = [&](int s) {
        uint32_t a_s = base + s * 16384;
        uint32_t b_s = a_s + 8192;
        #pragma unroll
        for (int kk = 0; kk < 2; kk++) {
            int ch = kk * 2 + chi;
            uint32_t a[4][4], b[2][4];
            #pragma unroll
            for (int im = 0; im < 4; im++)
                ldm_x4(a[im], a_s + arow[im] * 64 + ((ch ^ asw[im]) << 4));
            #pragma unroll
            for (int ib = 0; ib < 2; ib++)
                ldm_x4(b[ib], b_s + brow[ib] * 64 + ((ch ^ bsw[ib]) << 4));
            #pragma unroll
            for (int im = 0; im < 4; im++) {
                mma_bf16(acc[im][0], a[im], b[0][0], b[0][2]);
                mma_bf16(acc[im][1], a[im], b[0][1], b[0][3]);
                mma_bf16(acc[im][2], a[im], b[1][0], b[1][2]);
                mma_bf16(acc[im][3], a[im], b[1][1], b[1][3]);
            }
        }
    };

    load_stage(0, 0);
    load_stage(1, 1);
    #pragma unroll 1
    for (int ki = 0; ki < 16; ki++) {
        if (ki < 15) cp_wait<1>(); else cp_wait<0>();
        __syncthreads();
        if (ki + 2 < 16) load_stage(ki + 2, (ki + 2) % 3);
        compute(ki % 3);
    }

    // ---- epilogue: exp, per-(row,j) sums, e, scale, store ----
    const int qr = lane >> 2;
    const int qc = (lane & 3) * 2;
    const int jj = wn >> 6;  // 0 or 1: which local domain this warp's band is in
    #pragma unroll
    for (int im = 0; im < 4; im++) {
        int r0g = m0 + wm + im * 16 + qr;
        float h2a = g_h2[r0g], h2b = g_h2[r0g + 8];
        float rs0 = 0.f, rs1 = 0.f;
        #pragma unroll
        for (int in = 0; in < 4; in++) {
            int cg = n0 + wn + in * 8 + qc;
            float d2x = g_d2[cg], d2y = g_d2[cg + 1];
            float* c = acc[im][in];
            c[0] = expf(4.f * c[0] - 2.f * (h2a + d2x));
            c[1] = expf(4.f * c[1] - 2.f * (h2a + d2y));
            c[2] = expf(4.f * c[2] - 2.f * (h2b + d2x));
            c[3] = expf(4.f * c[3] - 2.f * (h2b + d2y));
            rs0 += c[0] + c[1];
            rs1 += c[2] + c[3];
        }
        rs0 += __shfl_xor_sync(0xffffffffu, rs0, 1);
        rs0 += __shfl_xor_sync(0xffffffffu, rs0, 2);
        rs1 += __shfl_xor_sync(0xffffffffu, rs1, 1);
        rs1 += __shfl_xor_sync(0xffffffffu, rs1, 2);
        if ((lane & 3) == 0) {
            atomicAdd(&jp[wm + im * 16 + qr][jj], rs0);
            atomicAdd(&jp[wm + im * 16 + qr + 8][jj], rs1);
        }
    }
    __syncthreads();
    if (tid < 256) {
        int rl = tid >> 1, j = tid & 1;
        float jsum = jp[rl][j];
        // mmd = 1 - 2*(jsum/64) + kdd; logit = -mmd
        float e = expf(jsum * (1.0f / 32.0f) - 1.0f - kddm[j]);
        es[rl][j] = e;
        g_e[(m0 + rl) * NJ + j0 + j] = e;
        atomicAdd(&g_Z[m0 + rl], e);
    }
    __syncthreads();
    #pragma unroll
    for (int im = 0; im < 4; im++) {
        int rl = wm + im * 16 + qr;
        int r0g = m0 + rl;
        float e0 = es[rl][jj], e1 = es[rl + 8][jj];
        #pragma unroll
        for (int in = 0; in < 4; in++) {
            int cg = n0 + wn + in * 8 + qc;
            float* c = acc[im][in];
            *(__nv_bfloat162*)&g_A2[(size_t)r0g * JM + cg] =
                __floats2bfloat162_rn(c[0] * e0, c[1] * e0);
            *(__nv_bfloat162*)&g_A2[(size_t)(r0g + 8) * JM + cg] =
                __floats2bfloat162_rn(c[2] * e1, c[3] * e1);
        }
    }
}

// ================= GEMM2: out = (A2 @ W + e @ bvec) / Z ==================
// 128x64 tile, BK=32, 4-stage cp.async, 256 threads (4m x 2n warps), 2 CTAs/SM
__global__ void __launch_bounds__(256, 2) gemm2_kernel(const float* __restrict__ bvec,
                                                       float* __restrict__ out) {
    extern __shared__ char smem[];
    __shared__ __nv_bfloat16 Ae[128][24];
    __shared__ __nv_bfloat16 Be[64][24];
    const int tid = threadIdx.x;
    const int lane = tid & 31, wid = tid >> 5;
    const int wm = (wid >> 1) * 32;    // 4 m bands
    const int wn = (wid & 1) * 32;     // 2 n bands
    const int m0 = blockIdx.y * 128;
    const int n0 = blockIdx.x * 64;

    uint32_t base = (uint32_t)__cvta_generic_to_shared(smem);
    uint32_t Bs_base = base + 32768;   // 4 x 4KB after 4 x 8KB A stages
    uint32_t Ae_base = (uint32_t)__cvta_generic_to_shared(Ae);
    uint32_t Be_base = (uint32_t)__cvta_generic_to_shared(Be);

    // stage e (bf16) and bvec^T (bf16)
    for (int idx = tid; idx < 128 * 16; idx += 256) {
        int rr = idx >> 4, j = idx & 15;
        Ae[rr][j] = __float2bfloat16(g_e[(size_t)(m0 + rr) * NJ + j]);
        if (rr < 64) Be[rr][j] = __float2bfloat16(bvec[(size_t)j * NU + n0 + rr]);
    }

    const int rlo = lane & 15, chi = lane >> 4;
    int arow[2], asw[2];
    #pragma unroll
    for (int im = 0; im < 2; im++) { arow[im] = wm + im * 16 + rlo; asw[im] = (arow[im] >> 1) & 3; }

    float acc[2][4][4] = {};

    auto load_stage = [&](int ki, int s) {
        const __nv_bfloat16* asrc = g_A2 + (size_t)m0 * JM + ki * 32;
        const __nv_bfloat16* bsrc = g_Wb + (size_t)ki * 32 * NU + n0;
        uint32_t a_s = base + s * 8192;
        uint32_t b_s = Bs_base + s * 4096;
        #pragma unroll
        for (int i = 0; i < 2; i++) {
            int lin = tid + i * 256;
            int r = lin >> 2, c = lin & 3;
            cp16(a_s + r * 64 + ((c ^ ((r >> 1) & 3)) << 4),
                 asrc + (size_t)r * JM + c * 8);
        }
        {
            int r = tid >> 3, c = tid & 7;   // 32 rows x 8 chunks = 256
            cp16(b_s + r * 128 + ((c ^ (r & 7)) << 4),
                 bsrc + (size_t)r * NU + c * 8);
        }
        cp_commit();
    };

    auto compute = [&](int s) {
        uint32_t a_s = base + s * 8192;
        uint32_t b_s = Bs_base + s * 4096;
        #pragma unroll
        for (int kk = 0; kk < 2; kk++) {
            int ch = kk * 2 + chi;
            uint32_t a[2][4], b[2][4];
            #pragma unroll
            for (int im = 0; im < 2; im++)
                ldm_x4(a[im], a_s + arow[im] * 64 + ((ch ^ asw[im]) << 4));
            #pragma unroll
            for (int ib = 0; ib < 2; ib++) {
                int row = kk * 16 + rlo;
                int cb = (wn >> 3) + ib * 2 + chi;
                ldm_x4t(b[ib], b_s + row * 128 + ((cb ^ (row & 7)) << 4));
            }
            #pragma unroll
            for (int im = 0; im < 2; im++) {
                mma_bf16(acc[im][0], a[im], b[0][0], b[0][1]);
                mma_bf16(acc[im][1], a[im], b[0][2], b[0][3]);
                mma_bf16(acc[im][2], a[im], b[1][0], b[1][1]);
                mma_bf16(acc[im][3], a[im], b[1][2], b[1][3]);
            }
        }
    };

    load_stage(0, 0);
    load_stage(1, 1);
    load_stage(2, 2);
    #pragma unroll 1
    for (int ki = 0; ki < 32; ki++) {
        if (ki < 29) cp_wait<2>(); else cp_wait<0>();
        __syncthreads();
        if (ki + 3 < 32) load_stage(ki + 3, (ki + 3) & 3);
        compute(ki & 3);
    }

    // ---- bias fold: one extra k16 step with A'=e(bf16), B'=bvec^T ----
    {
        uint32_t b[2][4];
        #pragma unroll
        for (int ib = 0; ib < 2; ib++) {
            int row = wn + ib * 16 + rlo;
            ldm_x4(b[ib], Be_base + row * 48 + chi * 16);
        }
        #pragma unroll
        for (int im = 0; im < 2; im++) {
            uint32_t a[4];
            int row = wm + im * 16 + rlo;
            ldm_x4(a, Ae_base + row * 48 + chi * 16);
            mma_bf16(acc[im][0], a, b[0][0], b[0][2]);
            mma_bf16(acc[im][1], a, b[0][1], b[0][3]);
            mma_bf16(acc[im][2], a, b[1][0], b[1][2]);
            mma_bf16(acc[im][3], a, b[1][1], b[1][3]);
        }
    }

    // epilogue: divide by Z, store
    const int qr = lane >> 2;
    const int qc = (lane & 3) * 2;
    #pragma unroll
    for (int im = 0; im < 2; im++) {
        int r0g = m0 + wm + im * 16 + qr;
        float zi0 = 1.0f / g_Z[r0g];
        float zi1 = 1.0f / g_Z[r0g + 8];
        #pragma unroll
        for (int in = 0; in < 4; in++) {
            int cg = n0 + wn + in * 8 + qc;
            float* c = acc[im][in];
            float2 v0 = {c[0] * zi0, c[1] * zi0};
            float2 v1 = {c[2] * zi1, c[3] * zi1};
            *(float2*)&out[(size_t)r0g * NU + cg] = v0;
            *(float2*)&out[(size_t)(r0g + 8) * NU + cg] = v1;
        }
    }
}

// ============================================================
extern "C" void kernel_launch(void* const* d_in, const int* in_sizes, int n_in,
                              void* d_out, int out_size) {
    const float* h    = (const float*)d_in[0];   // [B, F]
    const float* dom  = (const float*)d_in[1];   // [J, M, F]
    const float* W    = (const float*)d_in[2];   // [J, M, U]
    const float* bvec = (const float*)d_in[3];   // [J, U]
    float* out = (float*)d_out;                  // [B, U]

    cudaFuncSetAttribute(gemm1_kernel, cudaFuncAttributeMaxDynamicSharedMemorySize, 49152);
    cudaFuncSetAttribute(gemm2_kernel, cudaFuncAttributeMaxDynamicSharedMemorySize, 49152);

    prep_kernel<<<BATCH + 2 * JM, 128>>>(h, dom, W);
    kdd_kernel<<<dim3(NJ, 8), 128>>>(dom);
    gemm1_kernel<<<dim3(JM / 128, BATCH / 128), 256, 49152>>>();
    gemm2_kernel<<<dim3(NU / 64, BATCH / 128), 256, 49152>>>(bvec, out);
}